// round 13
// baseline (speedup 1.0000x reference)
#include <cuda_runtime.h>
#include <math.h>

// Problem constants (fixed by the reference setup)
#define NN    64      // batch per view
#define CC    256     // channels (contraction dim)
#define KK    196     // k-side positions (always 14x14 global proj)
#define QT    16      // q rows per tile
#define TERMS 14      // (j,i) term pairs

__device__ float g_vals[TERMS * NN];

__global__ __launch_bounds__(256, 1)
void term_kernel(const float* __restrict__ gl_sa,
                 const float* __restrict__ lo_sa,
                 const float* __restrict__ gl_pr,
                 const float* __restrict__ coords)
{
    extern __shared__ float sm[];
    float* kf  = sm;                  // CC*KK floats (full k sample)
    float* qs  = kf + CC * KK;        // CC*QT floats  (q tile, [c][rl])
    float* ckx = qs + CC * QT;        // KK
    float* cky = ckx + KK;            // KK
    float* red = cky + KK;            // 24 floats reduction scratch
    float* rowbuf = qs;               // alias: QT*KK (3136) <= CC*QT (4096)

    const int tid  = threadIdx.x;
    const int wid  = tid >> 5;
    const int lane = tid & 31;
    const int n = blockIdx.x;
    const int t = blockIdx.y;
    const int j = t / 7;
    const int r = t % 7;
    const bool is_gl = (r == 0);
    const int i = is_gl ? (1 - j) : (r - 1);
    const int Hq = is_gl ? 14 : 10;
    const int Q  = Hq * Hq;

    const float* qmap = is_gl ? (gl_sa + (size_t)(i * NN + n) * CC * 196)
                              : (lo_sa + (size_t)(i * NN + n) * CC * 100);
    const float* kmap = gl_pr + (size_t)(j * NN + n) * CC * KK;
    const float* cq = coords + (size_t)((is_gl ? i : 2 + i) * NN + n) * 4;
    const float* ck = coords + (size_t)(j * NN + n) * 4;

    // Per-sample geometry scalars
    const float cq0 = cq[0], cq1 = cq[1];
    const float bwq = (cq[2] - cq0) / (float)Hq;
    const float bhq = (cq[3] - cq1) / (float)Hq;
    const float ck0 = ck[0], ck1 = ck[1];
    const float bwk = (ck[2] - ck0) / 14.0f;
    const float bhk = (ck[3] - ck1) / 14.0f;
    const float qd = sqrtf(bwq * bwq + bhq * bhq);
    const float kd = sqrtf(bwk * bwk + bhk * bhk);
    const float rr = 0.7f * fmaxf(qd, kd);
    const float r2 = rr * rr;
    const float FINF = __int_as_float(0x7f800000);

    // Load full k sample into smem (contiguous, float4)
    {
        const float4* src = (const float4*)kmap;
        float4* dst = (float4*)kf;
        for (int idx = tid; idx < (CC * KK) / 4; idx += 256) dst[idx] = src[idx];
    }
    // k-side pixel centers
    if (tid < KK) {
        const int kx = tid % 14, ky = tid / 14;
        ckx[tid] = ((float)kx + 0.5f) * bwk + ck0;
        cky[tid] = ((float)ky + 0.5f) * bhk + ck1;
    }

    // GEMM thread mapping: 4 rowgroups x 64 col-threads, 4x4 register tile
    const int rg  = tid >> 6;     // 0..3 -> rows rg*4 .. rg*4+3 of the tile
    const int ct  = tid & 63;     // 0..63
    const int cc0 = ct * 4;       // col base; ct>=49 inactive (196 cols)
    const bool active = (cc0 < KK);

    float psum = 0.0f, pcnt = 0.0f, nacc = 0.0f;

    const int ntiles = (Q + QT - 1) / QT;
    for (int tile = 0; tile < ntiles; ++tile) {
        const int q0 = tile * QT;
        __syncthreads();  // previous rowbuf consumers done before q-tile reload

        // Load q tile: qs[c*QT + rl] = qmap[c*Q + q0+rl] (zero-pad invalid rows)
        for (int idx = tid; idx < CC * QT; idx += 256) {
            const int c = idx >> 4, rl = idx & (QT - 1);
            const int qq = q0 + rl;
            qs[idx] = (qq < Q) ? qmap[c * Q + qq] : 0.0f;
        }
        __syncthreads();

        float acc[4][4];
        #pragma unroll
        for (int a = 0; a < 4; ++a)
            #pragma unroll
            for (int b = 0; b < 4; ++b) acc[a][b] = 0.0f;

        if (active) {
            const float* qp = qs + rg * 4;
            const float* kp = kf + cc0;
            #pragma unroll 4
            for (int c = 0; c < CC; ++c) {
                const float4 qv = *(const float4*)(qp + c * QT);  // broadcast per warp
                const float4 kv = *(const float4*)(kp + c * KK);  // conflict-free
                acc[0][0] += qv.x * kv.x; acc[0][1] += qv.x * kv.y;
                acc[0][2] += qv.x * kv.z; acc[0][3] += qv.x * kv.w;
                acc[1][0] += qv.y * kv.x; acc[1][1] += qv.y * kv.y;
                acc[1][2] += qv.y * kv.z; acc[1][3] += qv.y * kv.w;
                acc[2][0] += qv.z * kv.x; acc[2][1] += qv.z * kv.y;
                acc[2][2] += qv.z * kv.z; acc[2][3] += qv.z * kv.w;
                acc[3][0] += qv.w * kv.x; acc[3][1] += qv.w * kv.y;
                acc[3][2] += qv.w * kv.z; acc[3][3] += qv.w * kv.w;
            }
        }
        __syncthreads();  // qs reads complete -> safe to overwrite as rowbuf

        // Mask, positives accumulation, masked-logit store for topk
        if (active) {
            #pragma unroll
            for (int a = 0; a < 4; ++a) {
                const int rl = rg * 4 + a;
                const int qq = q0 + rl;
                if (qq < Q) {
                    const int qx = qq % Hq, qy = qq / Hq;
                    const float cqx = ((float)qx + 0.5f) * bwq + cq0;
                    const float cqy = ((float)qy + 0.5f) * bhq + cq1;
                    float o0, o1, o2, o3;
                    float out4[4];
                    #pragma unroll
                    for (int b = 0; b < 4; ++b) {
                        const int cc = cc0 + b;
                        const float dx = cqx - ckx[cc];
                        const float dy = cqy - cky[cc];
                        float logit = -2.0f * acc[a][b];
                        if (dx * dx + dy * dy < r2) {   // dist < POS_RATIO
                            psum += logit; pcnt += 1.0f; logit = FINF;
                        }
                        out4[b] = logit;
                    }
                    o0 = out4[0]; o1 = out4[1]; o2 = out4[2]; o3 = out4[3];
                    *(float4*)(rowbuf + rl * KK + cc0) = make_float4(o0, o1, o2, o3);
                }
            }
        }
        __syncthreads();

        // Bottom-10 per q row (drop min, sum next 9). One warp per 2 rows.
        #pragma unroll
        for (int rw = 0; rw < 2; ++rw) {
            const int rl = wid * 2 + rw;
            const int qq = q0 + rl;
            if (qq < Q) {                    // uniform per warp
                float v[7];
                #pragma unroll
                for (int u = 0; u < 7; ++u) {
                    const int p = u * 32 + lane;
                    v[u] = (p < KK) ? rowbuf[rl * KK + p] : FINF;
                }
                float rowsum = 0.0f;
                for (int round = 0; round < 10; ++round) {
                    unsigned long long best = 0xFFFFFFFFFFFFFFFFull;
                    #pragma unroll
                    for (int u = 0; u < 7; ++u) {
                        const unsigned bits = __float_as_uint(v[u]);
                        const unsigned ord =
                            bits ^ ((bits >> 31) ? 0xFFFFFFFFu : 0x80000000u);
                        const unsigned long long key =
                            ((unsigned long long)ord << 32) | (unsigned)(u * 32 + lane);
                        best = (key < best) ? key : best;
                    }
                    #pragma unroll
                    for (int off = 16; off > 0; off >>= 1) {
                        const unsigned long long o =
                            __shfl_xor_sync(0xFFFFFFFFu, best, off);
                        best = (o < best) ? o : best;
                    }
                    const unsigned gp = (unsigned)best;          // u*32+lane of winner
                    if ((int)(gp & 31u) == lane) v[gp >> 5] = FINF;  // remove one instance
                    if (round > 0) {
                        const unsigned ord = (unsigned)(best >> 32);
                        const unsigned bits =
                            (ord & 0x80000000u) ? (ord ^ 0x80000000u) : ~ord;
                        rowsum += __uint_as_float(bits);
                    }
                }
                nacc += rowsum;   // uniform across lanes
            }
        }
    }

    // Block reduction: psum/pcnt per thread, nacc per warp
    #pragma unroll
    for (int off = 16; off > 0; off >>= 1) {
        psum += __shfl_xor_sync(0xFFFFFFFFu, psum, off);
        pcnt += __shfl_xor_sync(0xFFFFFFFFu, pcnt, off);
    }
    if (lane == 0) { red[wid] = psum; red[8 + wid] = pcnt; red[16 + wid] = nacc; }
    __syncthreads();
    if (tid == 0) {
        float ps = 0.0f, pc = 0.0f, ns = 0.0f;
        #pragma unroll
        for (int w = 0; w < 8; ++w) { ps += red[w]; pc += red[8 + w]; ns += red[16 + w]; }
        const float positives = ps / (pc + 1e-6f);
        const float negatives = (ns / 9.0f) / (float)Q;
        const float val = fmaxf(0.0f, -(negatives - 2.0f * positives) + 100.0f);
        g_vals[t * NN + n] = val;
    }
}

__global__ void finalize_kernel(float* __restrict__ out)
{
    __shared__ double s[256];
    const int tid = threadIdx.x;
    double acc = 0.0;
    for (int idx = tid; idx < TERMS * NN; idx += 256) acc += (double)g_vals[idx];
    s[tid] = acc;
    __syncthreads();
    for (int off = 128; off > 0; off >>= 1) {
        if (tid < off) s[tid] += s[tid + off];
        __syncthreads();
    }
    if (tid == 0) out[0] = (float)(s[0] / (double)(TERMS * NN));
}

extern "C" void kernel_launch(void* const* d_in, const int* in_sizes, int n_in,
                              void* d_out, int out_size)
{
    (void)in_sizes; (void)n_in; (void)out_size;
    const float* gl_sa  = (const float*)d_in[0];
    const float* lo_sa  = (const float*)d_in[1];
    const float* gl_pr  = (const float*)d_in[2];
    const float* coords = (const float*)d_in[3];

    const size_t smem = (size_t)(CC * KK + CC * QT + KK + KK + 32) * sizeof(float); // 218784 B
    cudaFuncSetAttribute((const void*)term_kernel,
                         cudaFuncAttributeMaxDynamicSharedMemorySize, (int)smem);

    term_kernel<<<dim3(NN, TERMS), 256, smem>>>(gl_sa, lo_sa, gl_pr, coords);
    finalize_kernel<<<1, 256>>>((float*)d_out);
}

// round 14
// speedup vs baseline: 1.5356x; 1.5356x over previous
#include <cuda_runtime.h>
#include <math.h>

// Problem constants (fixed by the reference setup)
#define NN    64      // batch per view
#define CC    256     // channels (contraction dim)
#define KK    196     // k-side positions (always 14x14 global proj)
#define QT    20      // q rows per tile
#define RG    5       // rowgroups (4 rows each)
#define CT    49      // col-threads per rowgroup (4 cols each -> 196)
#define ACT   (RG*CT) // 245 active GEMM threads
#define SLOTS 16      // 14 terms (chunk0) + 2 heavy chunk1

__device__ float g_ps[SLOTS * NN];
__device__ float g_pc[SLOTS * NN];
__device__ float g_ns[SLOTS * NN];

__global__ __launch_bounds__(256, 1)
void term_kernel(const float* __restrict__ gl_sa,
                 const float* __restrict__ lo_sa,
                 const float* __restrict__ gl_pr,
                 const float* __restrict__ coords)
{
    extern __shared__ float sm[];
    float* kf  = sm;                  // CC*KK floats (full k sample)
    float* qs  = kf + CC * KK;        // CC*QT floats (q tile, [c][rl], stride QT)
    float* ckx = qs + CC * QT;        // KK
    float* cky = ckx + KK;            // KK
    float* red = cky + KK;            // 32 floats reduction scratch
    float* rowbuf = qs;               // alias: QT*KK (3920) <= CC*QT (5120)

    const int tid  = threadIdx.x;
    const int wid  = tid >> 5;
    const int lane = tid & 31;
    const int n = blockIdx.x;
    const int s = blockIdx.y;              // slot
    const int t     = (s < 14) ? s : ((s == 14) ? 0 : 7);
    const int chunk = (s < 14) ? 0 : 1;
    const int j = t / 7;
    const int r = t % 7;
    const bool is_gl = (r == 0);
    const int i = is_gl ? (1 - j) : (r - 1);
    const int Hq = is_gl ? 14 : 10;
    const int Q  = Hq * Hq;

    const float* qmap = is_gl ? (gl_sa + (size_t)(i * NN + n) * CC * 196)
                              : (lo_sa + (size_t)(i * NN + n) * CC * 100);
    const float* kmap = gl_pr + (size_t)(j * NN + n) * CC * KK;
    const float* cq = coords + (size_t)((is_gl ? i : 2 + i) * NN + n) * 4;
    const float* ck = coords + (size_t)(j * NN + n) * 4;

    // Per-sample geometry scalars
    const float cq0 = cq[0], cq1 = cq[1];
    const float bwq = (cq[2] - cq0) / (float)Hq;
    const float bhq = (cq[3] - cq1) / (float)Hq;
    const float ck0 = ck[0], ck1 = ck[1];
    const float bwk = (ck[2] - ck0) / 14.0f;
    const float bhk = (ck[3] - ck1) / 14.0f;
    const float qd = sqrtf(bwq * bwq + bhq * bhq);
    const float kd = sqrtf(bwk * bwk + bhk * bhk);
    const float rr = 0.7f * fmaxf(qd, kd);
    const float r2 = rr * rr;
    const float FINF = __int_as_float(0x7f800000);

    // Load full k sample into smem (contiguous, float4)
    {
        const float4* src = (const float4*)kmap;
        float4* dst = (float4*)kf;
        #pragma unroll 4
        for (int idx = tid; idx < (CC * KK) / 4; idx += 256) dst[idx] = src[idx];
    }
    // k-side pixel centers
    if (tid < KK) {
        const int kx = tid % 14, ky = tid / 14;
        ckx[tid] = ((float)kx + 0.5f) * bwk + ck0;
        cky[tid] = ((float)ky + 0.5f) * bhk + ck1;
    }

    // GEMM thread mapping: 5 rowgroups x 49 col-threads, 4x4 register tile
    const bool active = (tid < ACT);
    const int rg  = tid / CT;         // 0..4 -> rows rg*4 .. rg*4+3 of the tile
    const int ct  = tid - rg * CT;    // 0..48
    const int cc0 = ct * 4;           // col base (exactly covers 196)

    float psum = 0.0f, pcnt = 0.0f, nacc = 0.0f;

    #pragma unroll 1
    for (int tile = 0; tile < 5; ++tile) {
        const int qrow0 = chunk * 100 + tile * QT;   // global q row base
        const int vr = min(QT, Q - qrow0);           // valid rows this tile
        __syncthreads();  // previous rowbuf consumers done before q-tile reload

        // Load q tile: qs[c*QT + rl] = qmap[c*Q + qrow0+rl]
        if (vr == QT) {
            // fast path: 5 float4 per channel row (alignment holds: Q%4==0, qrow0%20==0)
            for (int idx = tid; idx < CC * (QT / 4); idx += 256) {
                const int c = idx / 5, f = idx - c * 5;
                *(float4*)(qs + c * QT + f * 4) =
                    *(const float4*)(qmap + c * Q + qrow0 + f * 4);
            }
        } else {
            for (int idx = tid; idx < CC * QT; idx += 256) {
                const int c = idx / QT, rl = idx - c * QT;
                qs[idx] = (rl < vr) ? qmap[c * Q + qrow0 + rl] : 0.0f;
            }
        }
        __syncthreads();

        float acc[4][4];
        #pragma unroll
        for (int a = 0; a < 4; ++a)
            #pragma unroll
            for (int b = 0; b < 4; ++b) acc[a][b] = 0.0f;

        if (active) {
            const float* qp = qs + rg * 4;
            const float* kp = kf + cc0;
            #pragma unroll 4
            for (int c = 0; c < CC; ++c) {
                const float4 qv = *(const float4*)(qp + c * QT);  // near-broadcast
                const float4 kv = *(const float4*)(kp + c * KK);  // conflict-free
                acc[0][0] += qv.x * kv.x; acc[0][1] += qv.x * kv.y;
                acc[0][2] += qv.x * kv.z; acc[0][3] += qv.x * kv.w;
                acc[1][0] += qv.y * kv.x; acc[1][1] += qv.y * kv.y;
                acc[1][2] += qv.y * kv.z; acc[1][3] += qv.y * kv.w;
                acc[2][0] += qv.z * kv.x; acc[2][1] += qv.z * kv.y;
                acc[2][2] += qv.z * kv.z; acc[2][3] += qv.z * kv.w;
                acc[3][0] += qv.w * kv.x; acc[3][1] += qv.w * kv.y;
                acc[3][2] += qv.w * kv.z; acc[3][3] += qv.w * kv.w;
            }
        }
        __syncthreads();  // qs reads complete -> safe to overwrite as rowbuf

        // Mask, positives accumulation, masked-logit store for topk
        if (active) {
            #pragma unroll
            for (int a = 0; a < 4; ++a) {
                const int rl = rg * 4 + a;
                if (rl < vr) {
                    const int qq = qrow0 + rl;
                    const int qx = qq % Hq, qy = qq / Hq;
                    const float cqx = ((float)qx + 0.5f) * bwq + cq0;
                    const float cqy = ((float)qy + 0.5f) * bhq + cq1;
                    float out4[4];
                    #pragma unroll
                    for (int b = 0; b < 4; ++b) {
                        const int cc = cc0 + b;
                        const float dx = cqx - ckx[cc];
                        const float dy = cqy - cky[cc];
                        float logit = -2.0f * acc[a][b];
                        if (dx * dx + dy * dy < r2) {   // dist < POS_RATIO
                            psum += logit; pcnt += 1.0f; logit = FINF;
                        }
                        out4[b] = logit;
                    }
                    *(float4*)(rowbuf + rl * KK + cc0) =
                        make_float4(out4[0], out4[1], out4[2], out4[3]);
                }
            }
        }
        __syncthreads();

        // Bottom-10 per q row (drop min, sum next 9).
        // 32-bit keys: quantized sortable float (top 24 bits) | position (8 bits).
        #pragma unroll
        for (int rw = 0; rw < 3; ++rw) {
            const int rl = wid + rw * 8;
            if (rl < vr) {                    // uniform per warp
                unsigned k[7];
                #pragma unroll
                for (int u = 0; u < 7; ++u) {
                    const int p = u * 32 + lane;
                    if (p < KK) {
                        const unsigned bits =
                            __float_as_uint(rowbuf[rl * KK + p]);
                        const unsigned ord =
                            bits ^ ((bits & 0x80000000u) ? 0xFFFFFFFFu : 0x80000000u);
                        k[u] = (ord & 0xFFFFFF00u) | (unsigned)p;
                    } else {
                        k[u] = 0xFFFFFFFFu;
                    }
                }
                unsigned lmin = k[0];
                #pragma unroll
                for (int u = 1; u < 7; ++u) lmin = min(lmin, k[u]);

                float rowsum = 0.0f;
                for (int round = 0; round < 10; ++round) {
                    const unsigned m = __reduce_min_sync(0xFFFFFFFFu, lmin);
                    if (round > 0) {
                        const unsigned ordq = m & 0xFFFFFF00u;
                        const unsigned bits =
                            (ordq & 0x80000000u) ? (ordq ^ 0x80000000u) : ~ordq;
                        rowsum += __uint_as_float(bits);
                    }
                    const unsigned p = m & 0xFFu;
                    if ((int)(p & 31u) == lane) {
                        k[p >> 5] = 0xFFFFFFFFu;
                        lmin = k[0];
                        #pragma unroll
                        for (int u = 1; u < 7; ++u) lmin = min(lmin, k[u]);
                    }
                }
                nacc += rowsum;   // uniform across lanes
            }
        }
    }

    // Block reduction: psum/pcnt per thread, nacc per warp (lane-uniform)
    #pragma unroll
    for (int off = 16; off > 0; off >>= 1) {
        psum += __shfl_xor_sync(0xFFFFFFFFu, psum, off);
        pcnt += __shfl_xor_sync(0xFFFFFFFFu, pcnt, off);
    }
    if (lane == 0) { red[wid] = psum; red[8 + wid] = pcnt; red[16 + wid] = nacc; }
    __syncthreads();
    if (tid == 0) {
        float ps = 0.0f, pc = 0.0f, ns = 0.0f;
        #pragma unroll
        for (int w = 0; w < 8; ++w) { ps += red[w]; pc += red[8 + w]; ns += red[16 + w]; }
        g_ps[s * NN + n] = ps;
        g_pc[s * NN + n] = pc;
        g_ns[s * NN + n] = ns;
    }
}

__global__ void finalize_kernel(float* __restrict__ out)
{
    __shared__ double sred[256];
    const int tid = threadIdx.x;
    double acc = 0.0;
    for (int idx = tid; idx < 14 * NN; idx += 256) {
        const int t = idx / NN, n = idx - t * NN;
        float ps = g_ps[t * NN + n];
        float pc = g_pc[t * NN + n];
        float ns = g_ns[t * NN + n];
        if (t == 0) { ps += g_ps[14 * NN + n]; pc += g_pc[14 * NN + n]; ns += g_ns[14 * NN + n]; }
        if (t == 7) { ps += g_ps[15 * NN + n]; pc += g_pc[15 * NN + n]; ns += g_ns[15 * NN + n]; }
        const int Q = (t % 7 == 0) ? 196 : 100;
        const float positives = ps / (pc + 1e-6f);
        const float negatives = (ns / 9.0f) / (float)Q;
        acc += (double)fmaxf(0.0f, -(negatives - 2.0f * positives) + 100.0f);
    }
    sred[tid] = acc;
    __syncthreads();
    for (int off = 128; off > 0; off >>= 1) {
        if (tid < off) sred[tid] += sred[tid + off];
        __syncthreads();
    }
    if (tid == 0) out[0] = (float)(sred[0] / (double)(14 * NN));
}

extern "C" void kernel_launch(void* const* d_in, const int* in_sizes, int n_in,
                              void* d_out, int out_size)
{
    (void)in_sizes; (void)n_in; (void)out_size;
    const float* gl_sa  = (const float*)d_in[0];
    const float* lo_sa  = (const float*)d_in[1];
    const float* gl_pr  = (const float*)d_in[2];
    const float* coords = (const float*)d_in[3];

    const size_t smem = (size_t)(CC * KK + CC * QT + KK + KK + 32) * sizeof(float); // 222880 B
    cudaFuncSetAttribute((const void*)term_kernel,
                         cudaFuncAttributeMaxDynamicSharedMemorySize, (int)smem);

    term_kernel<<<dim3(NN, SLOTS), 256, smem>>>(gl_sa, lo_sa, gl_pr, coords);
    finalize_kernel<<<1, 256>>>((float*)d_out);
}

// round 16
// speedup vs baseline: 2.2390x; 1.4580x over previous
#include <cuda_runtime.h>
#include <cuda_bf16.h>
#include <math.h>
#include <stdint.h>

#define NN 64
#define CC 256
#define KK 196
#define SLOTS 16
#define RS 197            // rowbuf row stride (floats), odd -> conflict-free
#define PADK 72           // bf16 per smem row (144B stride: ldmatrix conflict-free)
#define NT 25             // n-tiles of 8 (covers 196, pad to 200)

// smem byte offsets
#define OFF_RED   0
#define OFF_CKX   128
#define OFF_CKY   912
#define OFF_AHI   1792                     // 128 * PADK * 2 = 18432
#define OFF_ALO   (OFF_AHI + 18432)
#define OFF_BHI   (OFF_ALO + 18432)        // 208 * PADK * 2 = 29952
#define OFF_BLO   (OFF_BHI + 29952)
#define SMEM_BYTES (OFF_BLO + 29952)       // 98560
#define OFF_ROWBUF OFF_AHI                 // alias after GEMM (100*197*4 = 78800)

__device__ float g_ps[SLOTS * NN];
__device__ float g_pc[SLOTS * NN];
__device__ float g_ns[SLOTS * NN];

__device__ __forceinline__ uint32_t smem_to_u32(const void* p) {
    uint32_t a;
    asm("{ .reg .u64 t; cvta.to.shared.u64 t, %1; cvt.u32.u64 %0, t; }"
        : "=r"(a) : "l"(p));
    return a;
}

__device__ __forceinline__ unsigned pack_split(float x0, float x1, unsigned& lop) {
    __nv_bfloat16 h0 = __float2bfloat16(x0);
    __nv_bfloat16 h1 = __float2bfloat16(x1);
    __nv_bfloat16 l0 = __float2bfloat16(x0 - __bfloat162float(h0));
    __nv_bfloat16 l1 = __float2bfloat16(x1 - __bfloat162float(h1));
    lop = (unsigned)__bfloat16_as_ushort(l0) | ((unsigned)__bfloat16_as_ushort(l1) << 16);
    return (unsigned)__bfloat16_as_ushort(h0) | ((unsigned)__bfloat16_as_ushort(h1) << 16);
}

#define LDSM_X4(r0, r1, r2, r3, a) \
    asm volatile("ldmatrix.sync.aligned.m8n8.x4.shared.b16 {%0,%1,%2,%3}, [%4];" \
        : "=r"(r0), "=r"(r1), "=r"(r2), "=r"(r3) : "r"(a))
#define LDSM_X2(r0, r1, a) \
    asm volatile("ldmatrix.sync.aligned.m8n8.x2.shared.b16 {%0,%1}, [%2];" \
        : "=r"(r0), "=r"(r1) : "r"(a))
#define MMA_BF16(d, a0, a1, a2, a3, b0, b1) \
    asm volatile("mma.sync.aligned.m16n8k16.row.col.f32.bf16.bf16.f32 " \
        "{%0,%1,%2,%3}, {%4,%5,%6,%7}, {%8,%9}, {%0,%1,%2,%3};" \
        : "+f"((d)[0]), "+f"((d)[1]), "+f"((d)[2]), "+f"((d)[3]) \
        : "r"(a0), "r"(a1), "r"(a2), "r"(a3), "r"(b0), "r"(b1))

__global__ __launch_bounds__(256, 1)
void term_kernel(const float* __restrict__ gl_sa,
                 const float* __restrict__ lo_sa,
                 const float* __restrict__ gl_pr,
                 const float* __restrict__ coords)
{
    extern __shared__ unsigned char smem[];
    const uint32_t sb = smem_to_u32(smem);
    float* red = (float*)(smem + OFF_RED);
    float* ckx = (float*)(smem + OFF_CKX);
    float* cky = (float*)(smem + OFF_CKY);
    float* rowbuf = (float*)(smem + OFF_ROWBUF);

    const int tid  = threadIdx.x;
    const int wid  = tid >> 5;
    const int lane = tid & 31;
    const int n = blockIdx.x;
    const int s = blockIdx.y;
    const int t     = (s < 14) ? s : ((s == 14) ? 0 : 7);
    const int chunkq = (s < 14) ? 0 : 1;
    const int j = t / 7;
    const int r = t % 7;
    const bool is_gl = (r == 0);
    const int i = is_gl ? (1 - j) : (r - 1);
    const int Hq = is_gl ? 14 : 10;
    const int Q  = Hq * Hq;
    const int qbase = chunkq * 100;
    const int vr = min(100, Q - qbase);

    const float* qmap = is_gl ? (gl_sa + (size_t)(i * NN + n) * CC * 196)
                              : (lo_sa + (size_t)(i * NN + n) * CC * 100);
    const float* kmap = gl_pr + (size_t)(j * NN + n) * CC * KK;
    const float* cq = coords + (size_t)((is_gl ? i : 2 + i) * NN + n) * 4;
    const float* ck = coords + (size_t)(j * NN + n) * 4;

    const float cq0 = cq[0], cq1 = cq[1];
    const float bwq = (cq[2] - cq0) / (float)Hq;
    const float bhq = (cq[3] - cq1) / (float)Hq;
    const float ck0 = ck[0], ck1 = ck[1];
    const float bwk = (ck[2] - ck0) / 14.0f;
    const float bhk = (ck[3] - ck1) / 14.0f;
    const float qd = sqrtf(bwq * bwq + bhq * bhq);
    const float kd = sqrtf(bwk * bwk + bhk * bhk);
    const float rr = 0.7f * fmaxf(qd, kd);
    const float r2 = rr * rr;
    const float FINF = __int_as_float(0x7f800000);

    if (tid < KK) {
        const int kx = tid % 14, ky = tid / 14;
        ckx[tid] = ((float)kx + 0.5f) * bwk + ck0;
        cky[tid] = ((float)ky + 0.5f) * bhk + ck1;
    }

    // lane mapping for transpose loads: 8 positions x 4 channel-pairs
    const int dn  = lane & 7;
    const int dc2 = (lane >> 3) << 1;

    float acc[NT][4];
    #pragma unroll
    for (int nt = 0; nt < NT; ++nt)
        #pragma unroll
        for (int b = 0; b < 4; ++b) acc[nt][b] = 0.0f;

    // ldmatrix lane-address components (constant across chunks)
    const int a_row  = lane & 15;               // A matrices: rows, then k+8
    const int a_koff = (lane >> 4) * 8;
    const int b_row  = lane & 7;                // B: 8 n-rows, koff 0 then 8
    const int b_koff = ((lane >> 3) & 1) * 8;
    const int warp_m = wid * 16;

    #pragma unroll 1
    for (int ch = 0; ch < 4; ++ch) {
        const int c0g = ch * 64;
        __syncthreads();   // previous chunk's ldmatrix reads done

        // ---- A chunk: As[q][c'] (transpose of qmap), 128 rows x 64 k ----
        for (int p = wid; p < 128; p += 8) {         // qb(16) x cpb(8)
            const int qb = p & 15, cpb = p >> 4;
            const int q  = qb * 8 + dn;
            const int c  = cpb * 8 + dc2;
            float x0 = 0.0f, x1 = 0.0f;
            if (q < vr) {
                x0 = qmap[(size_t)(c0g + c) * Q + qbase + q];
                x1 = qmap[(size_t)(c0g + c + 1) * Q + qbase + q];
            }
            unsigned lo;
            const unsigned hi = pack_split(x0, x1, lo);
            const unsigned off = (unsigned)(q * PADK + c) * 2u;
            *(unsigned*)(smem + OFF_AHI + off) = hi;
            *(unsigned*)(smem + OFF_ALO + off) = lo;
        }
        // ---- B chunk: Bn[nn][c'] (transpose of kmap), 208 rows x 64 k ----
        for (int p = wid; p < 208; p += 8) {         // nb(26) x cpb(8)
            const int nb = p % 26, cpb = p / 26;
            const int nn = nb * 8 + dn;
            const int c  = cpb * 8 + dc2;
            float x0 = 0.0f, x1 = 0.0f;
            if (nn < KK) {
                x0 = kmap[(size_t)(c0g + c) * KK + nn];
                x1 = kmap[(size_t)(c0g + c + 1) * KK + nn];
            }
            unsigned lo;
            const unsigned hi = pack_split(x0, x1, lo);
            const unsigned off = (unsigned)(nn * PADK + c) * 2u;
            *(unsigned*)(smem + OFF_BHI + off) = hi;
            *(unsigned*)(smem + OFF_BLO + off) = lo;
        }
        __syncthreads();

        // ---- MMA over 4 k-steps of 16 ----
        #pragma unroll
        for (int ks = 0; ks < 4; ++ks) {
            const uint32_t a_off =
                (uint32_t)((warp_m + a_row) * PADK + ks * 16 + a_koff) * 2u;
            uint32_t ah0, ah1, ah2, ah3, al0, al1, al2, al3;
            LDSM_X4(ah0, ah1, ah2, ah3, sb + OFF_AHI + a_off);
            LDSM_X4(al0, al1, al2, al3, sb + OFF_ALO + a_off);
            #pragma unroll
            for (int nt = 0; nt < NT; ++nt) {
                const uint32_t b_off =
                    (uint32_t)((nt * 8 + b_row) * PADK + ks * 16 + b_koff) * 2u;
                uint32_t bh0, bh1, bl0, bl1;
                LDSM_X2(bh0, bh1, sb + OFF_BHI + b_off);
                LDSM_X2(bl0, bl1, sb + OFF_BLO + b_off);
                MMA_BF16(acc[nt], ah0, ah1, ah2, ah3, bh0, bh1);
                MMA_BF16(acc[nt], al0, al1, al2, al3, bh0, bh1);
                MMA_BF16(acc[nt], ah0, ah1, ah2, ah3, bl0, bl1);
            }
        }
    }
    __syncthreads();   // all warps done with A/B smem -> safe to alias rowbuf

    // ---- Epilogue: mask + positives from fragments, spill masked logits ----
    float psum = 0.0f, pcnt = 0.0f, nacc = 0.0f;
    {
        const int r0 = warp_m + (lane >> 2);
        const int r1 = r0 + 8;
        const int cb = (lane & 3) * 2;
        float cqx0 = 0.0f, cqy0 = 0.0f, cqx1 = 0.0f, cqy1 = 0.0f;
        if (r0 < vr) {
            const int qq = qbase + r0;
            cqx0 = ((float)(qq % Hq) + 0.5f) * bwq + cq0;
            cqy0 = ((float)(qq / Hq) + 0.5f) * bhq + cq1;
        }
        if (r1 < vr) {
            const int qq = qbase + r1;
            cqx1 = ((float)(qq % Hq) + 0.5f) * bwq + cq0;
            cqy1 = ((float)(qq / Hq) + 0.5f) * bhq + cq1;
        }
        #pragma unroll
        for (int nt = 0; nt < NT; ++nt) {
            #pragma unroll
            for (int e = 0; e < 2; ++e) {
                const int cc = nt * 8 + cb + e;
                if (cc < KK) {
                    const float kx = ckx[cc], ky = cky[cc];
                    if (r0 < vr) {
                        float logit = -2.0f * acc[nt][e];
                        const float dx = cqx0 - kx, dy = cqy0 - ky;
                        if (dx * dx + dy * dy < r2) {
                            psum += logit; pcnt += 1.0f; logit = FINF;
                        }
                        rowbuf[r0 * RS + cc] = logit;
                    }
                    if (r1 < vr) {
                        float logit = -2.0f * acc[nt][2 + e];
                        const float dx = cqx1 - kx, dy = cqy1 - ky;
                        if (dx * dx + dy * dy < r2) {
                            psum += logit; pcnt += 1.0f; logit = FINF;
                        }
                        rowbuf[r1 * RS + cc] = logit;
                    }
                }
            }
        }
    }
    __syncthreads();

    // ---- Bottom-10 per row (drop min, sum next 9); one warp per row ----
    for (int rw = 0; rw < 13; ++rw) {
        const int rl = wid + rw * 8;
        if (rl < vr) {
            unsigned kreg[7];
            #pragma unroll
            for (int u = 0; u < 7; ++u) {
                const int p = u * 32 + lane;
                if (p < KK) {
                    const unsigned bits = __float_as_uint(rowbuf[rl * RS + p]);
                    const unsigned ord =
                        bits ^ ((bits & 0x80000000u) ? 0xFFFFFFFFu : 0x80000000u);
                    kreg[u] = (ord & 0xFFFFFF00u) | (unsigned)p;
                } else {
                    kreg[u] = 0xFFFFFFFFu;
                }
            }
            unsigned lmin = kreg[0];
            #pragma unroll
            for (int u = 1; u < 7; ++u) lmin = min(lmin, kreg[u]);
            float rowsum = 0.0f;
            for (int round = 0; round < 10; ++round) {
                const unsigned m2 = __reduce_min_sync(0xFFFFFFFFu, lmin);
                if (round > 0) {
                    const unsigned ordq = m2 & 0xFFFFFF00u;
                    const unsigned bits =
                        (ordq & 0x80000000u) ? (ordq ^ 0x80000000u) : ~ordq;
                    rowsum += __uint_as_float(bits);
                }
                const unsigned p = m2 & 0xFFu;
                if ((int)(p & 31u) == lane) {
                    kreg[p >> 5] = 0xFFFFFFFFu;
                    lmin = kreg[0];
                    #pragma unroll
                    for (int u = 1; u < 7; ++u) lmin = min(lmin, kreg[u]);
                }
            }
            nacc += rowsum;
        }
    }

    // ---- Reductions ----
    #pragma unroll
    for (int off = 16; off > 0; off >>= 1) {
        psum += __shfl_xor_sync(0xFFFFFFFFu, psum, off);
        pcnt += __shfl_xor_sync(0xFFFFFFFFu, pcnt, off);
    }
    if (lane == 0) { red[wid] = psum; red[8 + wid] = pcnt; red[16 + wid] = nacc; }
    __syncthreads();
    if (tid == 0) {
        float ps = 0.0f, pc = 0.0f, ns = 0.0f;
        #pragma unroll
        for (int w = 0; w < 8; ++w) { ps += red[w]; pc += red[8 + w]; ns += red[16 + w]; }
        g_ps[s * NN + n] = ps;
        g_pc[s * NN + n] = pc;
        g_ns[s * NN + n] = ns;
    }
}

__global__ void finalize_kernel(float* __restrict__ out)
{
    __shared__ double sred[256];
    const int tid = threadIdx.x;
    double acc = 0.0;
    for (int idx = tid; idx < 14 * NN; idx += 256) {
        const int t = idx / NN, n = idx - t * NN;
        float ps = g_ps[t * NN + n];
        float pc = g_pc[t * NN + n];
        float ns = g_ns[t * NN + n];
        if (t == 0) { ps += g_ps[14 * NN + n]; pc += g_pc[14 * NN + n]; ns += g_ns[14 * NN + n]; }
        if (t == 7) { ps += g_ps[15 * NN + n]; pc += g_pc[15 * NN + n]; ns += g_ns[15 * NN + n]; }
        const int Q = (t % 7 == 0) ? 196 : 100;
        const float positives = ps / (pc + 1e-6f);
        const float negatives = (ns / 9.0f) / (float)Q;
        acc += (double)fmaxf(0.0f, -(negatives - 2.0f * positives) + 100.0f);
    }
    sred[tid] = acc;
    __syncthreads();
    for (int off = 128; off > 0; off >>= 1) {
        if (tid < off) sred[tid] += sred[tid + off];
        __syncthreads();
    }
    if (tid == 0) out[0] = (float)(sred[0] / (double)(14 * NN));
}

extern "C" void kernel_launch(void* const* d_in, const int* in_sizes, int n_in,
                              void* d_out, int out_size)
{
    (void)in_sizes; (void)n_in; (void)out_size;
    const float* gl_sa  = (const float*)d_in[0];
    const float* lo_sa  = (const float*)d_in[1];
    const float* gl_pr  = (const float*)d_in[2];
    const float* coords = (const float*)d_in[3];

    cudaFuncSetAttribute((const void*)term_kernel,
                         cudaFuncAttributeMaxDynamicSharedMemorySize, SMEM_BYTES);

    term_kernel<<<dim3(NN, SLOTS), 256, SMEM_BYTES>>>(gl_sa, lo_sa, gl_pr, coords);
    finalize_kernel<<<1, 256>>>((float*)d_out);
}

// round 17
// speedup vs baseline: 2.2394x; 1.0002x over previous
#include <cuda_runtime.h>
#include <cuda_bf16.h>
#include <math.h>
#include <stdint.h>

#define NN 64
#define CC 256
#define KK 196
#define SLOTS 16
#define RS 197            // rowbuf row stride (floats), odd -> conflict-free
#define PADK 72           // bf16 per smem row (144B stride: ldmatrix conflict-free)
#define NT 25             // n-tiles of 8 (covers 196, pad to 200)

// smem byte offsets
#define OFF_RED   0
#define OFF_CKX   128
#define OFF_CKY   912
#define OFF_AHI   1792                     // 128 * PADK * 2 = 18432
#define OFF_ALO   (OFF_AHI + 18432)
#define OFF_BHI   (OFF_ALO + 18432)        // 208 * PADK * 2 = 29952
#define OFF_BLO   (OFF_BHI + 29952)
#define SMEM_BYTES (OFF_BLO + 29952)       // 98560
#define OFF_ROWBUF OFF_AHI                 // alias after GEMM (100*197*4 = 78800)

__device__ float g_ps[SLOTS * NN];
__device__ float g_pc[SLOTS * NN];
__device__ float g_ns[SLOTS * NN];

__device__ __forceinline__ uint32_t smem_to_u32(const void* p) {
    uint32_t a;
    asm("{ .reg .u64 t; cvta.to.shared.u64 t, %1; cvt.u32.u64 %0, t; }"
        : "=r"(a) : "l"(p));
    return a;
}

__device__ __forceinline__ unsigned pack_split(float x0, float x1, unsigned& lop) {
    __nv_bfloat16 h0 = __float2bfloat16(x0);
    __nv_bfloat16 h1 = __float2bfloat16(x1);
    __nv_bfloat16 l0 = __float2bfloat16(x0 - __bfloat162float(h0));
    __nv_bfloat16 l1 = __float2bfloat16(x1 - __bfloat162float(h1));
    lop = (unsigned)__bfloat16_as_ushort(l0) | ((unsigned)__bfloat16_as_ushort(l1) << 16);
    return (unsigned)__bfloat16_as_ushort(h0) | ((unsigned)__bfloat16_as_ushort(h1) << 16);
}

#define LDSM_X4(r0, r1, r2, r3, a) \
    asm volatile("ldmatrix.sync.aligned.m8n8.x4.shared.b16 {%0,%1,%2,%3}, [%4];" \
        : "=r"(r0), "=r"(r1), "=r"(r2), "=r"(r3) : "r"(a))
#define LDSM_X2(r0, r1, a) \
    asm volatile("ldmatrix.sync.aligned.m8n8.x2.shared.b16 {%0,%1}, [%2];" \
        : "=r"(r0), "=r"(r1) : "r"(a))
#define MMA_BF16(d, a0, a1, a2, a3, b0, b1) \
    asm volatile("mma.sync.aligned.m16n8k16.row.col.f32.bf16.bf16.f32 " \
        "{%0,%1,%2,%3}, {%4,%5,%6,%7}, {%8,%9}, {%0,%1,%2,%3};" \
        : "+f"((d)[0]), "+f"((d)[1]), "+f"((d)[2]), "+f"((d)[3]) \
        : "r"(a0), "r"(a1), "r"(a2), "r"(a3), "r"(b0), "r"(b1))

__global__ __launch_bounds__(256, 1)
void term_kernel(const float* __restrict__ gl_sa,
                 const float* __restrict__ lo_sa,
                 const float* __restrict__ gl_pr,
                 const float* __restrict__ coords)
{
    extern __shared__ unsigned char smem[];
    const uint32_t sb = smem_to_u32(smem);
    float* red = (float*)(smem + OFF_RED);
    float* ckx = (float*)(smem + OFF_CKX);
    float* cky = (float*)(smem + OFF_CKY);
    float* rowbuf = (float*)(smem + OFF_ROWBUF);

    const int tid  = threadIdx.x;
    const int wid  = tid >> 5;
    const int lane = tid & 31;
    const int n = blockIdx.x;
    const int s = blockIdx.y;
    const int t     = (s < 14) ? s : ((s == 14) ? 0 : 7);
    const int chunkq = (s < 14) ? 0 : 1;
    const int j = t / 7;
    const int r = t % 7;
    const bool is_gl = (r == 0);
    const int i = is_gl ? (1 - j) : (r - 1);
    const int Hq = is_gl ? 14 : 10;
    const int Q  = Hq * Hq;
    const int qbase = chunkq * 100;
    const int vr = min(100, Q - qbase);

    const float* qmap = is_gl ? (gl_sa + (size_t)(i * NN + n) * CC * 196)
                              : (lo_sa + (size_t)(i * NN + n) * CC * 100);
    const float* kmap = gl_pr + (size_t)(j * NN + n) * CC * KK;
    const float* cq = coords + (size_t)((is_gl ? i : 2 + i) * NN + n) * 4;
    const float* ck = coords + (size_t)(j * NN + n) * 4;

    const float cq0 = cq[0], cq1 = cq[1];
    const float bwq = (cq[2] - cq0) / (float)Hq;
    const float bhq = (cq[3] - cq1) / (float)Hq;
    const float ck0 = ck[0], ck1 = ck[1];
    const float bwk = (ck[2] - ck0) / 14.0f;
    const float bhk = (ck[3] - ck1) / 14.0f;
    const float qd = sqrtf(bwq * bwq + bhq * bhq);
    const float kd = sqrtf(bwk * bwk + bhk * bhk);
    const float rr = 0.7f * fmaxf(qd, kd);
    const float r2 = rr * rr;
    const float FINF = __int_as_float(0x7f800000);

    if (tid < KK) {
        const int kx = tid % 14, ky = tid / 14;
        ckx[tid] = ((float)kx + 0.5f) * bwk + ck0;
        cky[tid] = ((float)ky + 0.5f) * bhk + ck1;
    }

    // lane mapping for transpose loads: 8 positions x 4 channel-pairs
    const int dn  = lane & 7;
    const int dc2 = (lane >> 3) << 1;

    float acc[NT][4];
    #pragma unroll
    for (int nt = 0; nt < NT; ++nt)
        #pragma unroll
        for (int b = 0; b < 4; ++b) acc[nt][b] = 0.0f;

    // ldmatrix lane-address components (constant across chunks)
    const int a_row  = lane & 15;               // A matrices: rows, then k+8
    const int a_koff = (lane >> 4) * 8;
    const int b_row  = lane & 7;                // B: 8 n-rows, koff 0 then 8
    const int b_koff = ((lane >> 3) & 1) * 8;
    const int warp_m = wid * 16;

    #pragma unroll 1
    for (int ch = 0; ch < 4; ++ch) {
        const int c0g = ch * 64;
        __syncthreads();   // previous chunk's ldmatrix reads done

        // ---- A chunk: As[q][c'] (transpose of qmap), 128 rows x 64 k ----
        for (int p = wid; p < 128; p += 8) {         // qb(16) x cpb(8)
            const int qb = p & 15, cpb = p >> 4;
            const int q  = qb * 8 + dn;
            const int c  = cpb * 8 + dc2;
            float x0 = 0.0f, x1 = 0.0f;
            if (q < vr) {
                x0 = qmap[(size_t)(c0g + c) * Q + qbase + q];
                x1 = qmap[(size_t)(c0g + c + 1) * Q + qbase + q];
            }
            unsigned lo;
            const unsigned hi = pack_split(x0, x1, lo);
            const unsigned off = (unsigned)(q * PADK + c) * 2u;
            *(unsigned*)(smem + OFF_AHI + off) = hi;
            *(unsigned*)(smem + OFF_ALO + off) = lo;
        }
        // ---- B chunk: Bn[nn][c'] (transpose of kmap), 208 rows x 64 k ----
        for (int p = wid; p < 208; p += 8) {         // nb(26) x cpb(8)
            const int nb = p % 26, cpb = p / 26;
            const int nn = nb * 8 + dn;
            const int c  = cpb * 8 + dc2;
            float x0 = 0.0f, x1 = 0.0f;
            if (nn < KK) {
                x0 = kmap[(size_t)(c0g + c) * KK + nn];
                x1 = kmap[(size_t)(c0g + c + 1) * KK + nn];
            }
            unsigned lo;
            const unsigned hi = pack_split(x0, x1, lo);
            const unsigned off = (unsigned)(nn * PADK + c) * 2u;
            *(unsigned*)(smem + OFF_BHI + off) = hi;
            *(unsigned*)(smem + OFF_BLO + off) = lo;
        }
        __syncthreads();

        // ---- MMA over 4 k-steps of 16 ----
        #pragma unroll
        for (int ks = 0; ks < 4; ++ks) {
            const uint32_t a_off =
                (uint32_t)((warp_m + a_row) * PADK + ks * 16 + a_koff) * 2u;
            uint32_t ah0, ah1, ah2, ah3, al0, al1, al2, al3;
            LDSM_X4(ah0, ah1, ah2, ah3, sb + OFF_AHI + a_off);
            LDSM_X4(al0, al1, al2, al3, sb + OFF_ALO + a_off);
            #pragma unroll
            for (int nt = 0; nt < NT; ++nt) {
                const uint32_t b_off =
                    (uint32_t)((nt * 8 + b_row) * PADK + ks * 16 + b_koff) * 2u;
                uint32_t bh0, bh1, bl0, bl1;
                LDSM_X2(bh0, bh1, sb + OFF_BHI + b_off);
                LDSM_X2(bl0, bl1, sb + OFF_BLO + b_off);
                MMA_BF16(acc[nt], ah0, ah1, ah2, ah3, bh0, bh1);
                MMA_BF16(acc[nt], al0, al1, al2, al3, bh0, bh1);
                MMA_BF16(acc[nt], ah0, ah1, ah2, ah3, bl0, bl1);
            }
        }
    }
    __syncthreads();   // all warps done with A/B smem -> safe to alias rowbuf

    // ---- Epilogue: mask + positives from fragments, spill masked logits ----
    float psum = 0.0f, pcnt = 0.0f, nacc = 0.0f;
    {
        const int r0 = warp_m + (lane >> 2);
        const int r1 = r0 + 8;
        const int cb = (lane & 3) * 2;
        float cqx0 = 0.0f, cqy0 = 0.0f, cqx1 = 0.0f, cqy1 = 0.0f;
        if (r0 < vr) {
            const int qq = qbase + r0;
            cqx0 = ((float)(qq % Hq) + 0.5f) * bwq + cq0;
            cqy0 = ((float)(qq / Hq) + 0.5f) * bhq + cq1;
        }
        if (r1 < vr) {
            const int qq = qbase + r1;
            cqx1 = ((float)(qq % Hq) + 0.5f) * bwq + cq0;
            cqy1 = ((float)(qq / Hq) + 0.5f) * bhq + cq1;
        }
        #pragma unroll
        for (int nt = 0; nt < NT; ++nt) {
            #pragma unroll
            for (int e = 0; e < 2; ++e) {
                const int cc = nt * 8 + cb + e;
                if (cc < KK) {
                    const float kx = ckx[cc], ky = cky[cc];
                    if (r0 < vr) {
                        float logit = -2.0f * acc[nt][e];
                        const float dx = cqx0 - kx, dy = cqy0 - ky;
                        if (dx * dx + dy * dy < r2) {
                            psum += logit; pcnt += 1.0f; logit = FINF;
                        }
                        rowbuf[r0 * RS + cc] = logit;
                    }
                    if (r1 < vr) {
                        float logit = -2.0f * acc[nt][2 + e];
                        const float dx = cqx1 - kx, dy = cqy1 - ky;
                        if (dx * dx + dy * dy < r2) {
                            psum += logit; pcnt += 1.0f; logit = FINF;
                        }
                        rowbuf[r1 * RS + cc] = logit;
                    }
                }
            }
        }
    }
    __syncthreads();

    // ---- Bottom-10 per row (drop min, sum next 9); one warp per row ----
    for (int rw = 0; rw < 13; ++rw) {
        const int rl = wid + rw * 8;
        if (rl < vr) {
            unsigned kreg[7];
            #pragma unroll
            for (int u = 0; u < 7; ++u) {
                const int p = u * 32 + lane;
                if (p < KK) {
                    const unsigned bits = __float_as_uint(rowbuf[rl * RS + p]);
                    const unsigned ord =
                        bits ^ ((bits & 0x80000000u) ? 0xFFFFFFFFu : 0x80000000u);
                    kreg[u] = (ord & 0xFFFFFF00u) | (unsigned)p;
                } else {
                    kreg[u] = 0xFFFFFFFFu;
                }
            }
            unsigned lmin = kreg[0];
            #pragma unroll
            for (int u = 1; u < 7; ++u) lmin = min(lmin, kreg[u]);
            float rowsum = 0.0f;
            for (int round = 0; round < 10; ++round) {
                const unsigned m2 = __reduce_min_sync(0xFFFFFFFFu, lmin);
                if (round > 0) {
                    const unsigned ordq = m2 & 0xFFFFFF00u;
                    const unsigned bits =
                        (ordq & 0x80000000u) ? (ordq ^ 0x80000000u) : ~ordq;
                    rowsum += __uint_as_float(bits);
                }
                const unsigned p = m2 & 0xFFu;
                if ((int)(p & 31u) == lane) {
                    kreg[p >> 5] = 0xFFFFFFFFu;
                    lmin = kreg[0];
                    #pragma unroll
                    for (int u = 1; u < 7; ++u) lmin = min(lmin, kreg[u]);
                }
            }
            nacc += rowsum;
        }
    }

    // ---- Reductions ----
    #pragma unroll
    for (int off = 16; off > 0; off >>= 1) {
        psum += __shfl_xor_sync(0xFFFFFFFFu, psum, off);
        pcnt += __shfl_xor_sync(0xFFFFFFFFu, pcnt, off);
    }
    if (lane == 0) { red[wid] = psum; red[8 + wid] = pcnt; red[16 + wid] = nacc; }
    __syncthreads();
    if (tid == 0) {
        float ps = 0.0f, pc = 0.0f, ns = 0.0f;
        #pragma unroll
        for (int w = 0; w < 8; ++w) { ps += red[w]; pc += red[8 + w]; ns += red[16 + w]; }
        g_ps[s * NN + n] = ps;
        g_pc[s * NN + n] = pc;
        g_ns[s * NN + n] = ns;
    }
}

__global__ void finalize_kernel(float* __restrict__ out)
{
    __shared__ double sred[256];
    const int tid = threadIdx.x;
    double acc = 0.0;
    for (int idx = tid; idx < 14 * NN; idx += 256) {
        const int t = idx / NN, n = idx - t * NN;
        float ps = g_ps[t * NN + n];
        float pc = g_pc[t * NN + n];
        float ns = g_ns[t * NN + n];
        if (t == 0) { ps += g_ps[14 * NN + n]; pc += g_pc[14 * NN + n]; ns += g_ns[14 * NN + n]; }
        if (t == 7) { ps += g_ps[15 * NN + n]; pc += g_pc[15 * NN + n]; ns += g_ns[15 * NN + n]; }
        const int Q = (t % 7 == 0) ? 196 : 100;
        const float positives = ps / (pc + 1e-6f);
        const float negatives = (ns / 9.0f) / (float)Q;
        acc += (double)fmaxf(0.0f, -(negatives - 2.0f * positives) + 100.0f);
    }
    sred[tid] = acc;
    __syncthreads();
    for (int off = 128; off > 0; off >>= 1) {
        if (tid < off) sred[tid] += sred[tid + off];
        __syncthreads();
    }
    if (tid == 0) out[0] = (float)(sred[0] / (double)(14 * NN));
}

extern "C" void kernel_launch(void* const* d_in, const int* in_sizes, int n_in,
                              void* d_out, int out_size)
{
    (void)in_sizes; (void)n_in; (void)out_size;
    const float* gl_sa  = (const float*)d_in[0];
    const float* lo_sa  = (const float*)d_in[1];
    const float* gl_pr  = (const float*)d_in[2];
    const float* coords = (const float*)d_in[3];

    cudaFuncSetAttribute((const void*)term_kernel,
                         cudaFuncAttributeMaxDynamicSharedMemorySize, SMEM_BYTES);

    term_kernel<<<dim3(NN, SLOTS), 256, SMEM_BYTES>>>(gl_sa, lo_sa, gl_pr, coords);
    finalize_kernel<<<1, 256>>>((float*)d_out);
}